// round 12
// baseline (speedup 1.0000x reference)
#include <cuda_runtime.h>

#define NB 8
#define NS 2048
#define NE 8
#define NH 2
#define ND 4
#define NT (NB*NS)        // 16384 tokens
#define NBH (NB*NH)       // 16 (batch, head) pairs
#define SPLITS 8
#define KPS (NS/SPLITS)   // 256 keys per split
#define NPAIR (KPS/2)     // 128 key pairs
#define QB 256            // queries per CTA (2 per thread)
#define NQBLK (NS/QB)     // 8 query blocks
#define NCONTRIB (SPLITS*NH)  // 16 CTAs feed one (b, qblock)

// log2(e) / sqrt(D) folded into q so scores feed ex2 directly
#define QSCALE 0.72134752044448169f

// Accumulators + counters (zero at load; every launch restores zeros)
__device__ float4   g_accN[NT*NH];       // numerators, index = token*2 + head
__device__ float    g_accD[NT*NH];       // denominators
__device__ unsigned g_cnt[NB*NQBLK];     // completion counters

typedef unsigned long long ull;

// ---- packed f32x2 helpers ----
static __device__ __forceinline__ ull pack2(float a, float b) {
    ull r; asm("mov.b64 %0, {%1,%2};" : "=l"(r) : "f"(a), "f"(b)); return r;
}
static __device__ __forceinline__ void unpack2(ull v, float& a, float& b) {
    asm("mov.b64 {%0,%1}, %2;" : "=f"(a), "=f"(b) : "l"(v));
}
static __device__ __forceinline__ ull fma2p(ull a, ull b, ull c) {
    ull d; asm("fma.rn.f32x2 %0, %1, %2, %3;" : "=l"(d) : "l"(a), "l"(b), "l"(c)); return d;
}
static __device__ __forceinline__ ull mul2p(ull a, ull b) {
    ull d; asm("mul.rn.f32x2 %0, %1, %2;" : "=l"(d) : "l"(a), "l"(b)); return d;
}
static __device__ __forceinline__ float ex2f(float x) {
    float r; asm("ex2.approx.f32 %0, %1;" : "=f"(r) : "f"(x)); return r;
}
static __device__ __forceinline__ float rcpf(float x) {
    float r; asm("rcp.approx.f32 %0, %1;" : "=f"(r) : "f"(x)); return r;
}
static __device__ __forceinline__ void fence_gpu() {
    asm volatile("membar.gl;" ::: "memory");
}

// ============================================================
// Single fused kernel: QKV + split-K attention (R6/R11-proven
// mainloop) + atomic reduction + CHEAP semaphore (tid0-only
// fence per CTA, CUTLASS-style) + inline finalize by the last
// CTA per (b, qblock).
// grid = (NQBLK, SPLITS, NBH) = 1024 CTAs, 128 threads.
// ============================================================
__global__ void __launch_bounds__(128, 7) fused_kernel(const float* __restrict__ x,
                                                       const float* __restrict__ Wq,
                                                       const float* __restrict__ Wk,
                                                       const float* __restrict__ Wv,
                                                       const float* __restrict__ Wo,
                                                       float* __restrict__ out) {
    __shared__ float sWq[32], sWk[32], sWv[32];   // this head's 4 rows (4x8)
    __shared__ float sWo[64];
    __shared__ ulonglong2 sK01[NPAIR];
    __shared__ ulonglong2 sK23[NPAIR];
    __shared__ ulonglong2 sV01[NPAIR];
    __shared__ ulonglong2 sV23[NPAIR];
    __shared__ unsigned s_old;

    const int bh    = blockIdx.z;
    const int split = blockIdx.y;
    const int tid   = threadIdx.x;
    const int b     = bh >> 1;
    const int h     = bh & 1;

    if (tid < 32) {
        sWq[tid] = Wq[h*32 + tid];
        sWk[tid] = Wk[h*32 + tid];
        sWv[tid] = Wv[h*32 + tid];
    }
    if (tid >= 64) sWo[tid - 64] = Wo[tid - 64];
    __syncthreads();

    const float4* x4 = (const float4*)x;

    // ---- stage one key pair per thread (keys 2*tid, 2*tid+1) ----
    {
        int tokA = b*NS + split*KPS + 2*tid;
        float4 a0 = x4[tokA*2], a1 = x4[tokA*2+1];
        float4 b0 = x4[tokA*2+2], b1 = x4[tokA*2+3];
        float xra[8] = {a0.x,a0.y,a0.z,a0.w,a1.x,a1.y,a1.z,a1.w};
        float xrb[8] = {b0.x,b0.y,b0.z,b0.w,b1.x,b1.y,b1.z,b1.w};
        float kA[4], vA[4], kB[4], vB[4];
#pragma unroll
        for (int d = 0; d < 4; d++) {
            float ka = 0.f, va = 0.f, kb = 0.f, vb = 0.f;
#pragma unroll
            for (int e = 0; e < 8; e++) {
                float wk = sWk[d*8 + e], wv = sWv[d*8 + e];
                ka += xra[e] * wk;  va += xra[e] * wv;
                kb += xrb[e] * wk;  vb += xrb[e] * wv;
            }
            kA[d] = ka; vA[d] = va; kB[d] = kb; vB[d] = vb;
        }
        ulonglong2 t;
        t.x = pack2(kA[0], kB[0]); t.y = pack2(kA[1], kB[1]); sK01[tid] = t;
        t.x = pack2(kA[2], kB[2]); t.y = pack2(kA[3], kB[3]); sK23[tid] = t;
        t.x = pack2(vA[0], vB[0]); t.y = pack2(vA[1], vB[1]); sV01[tid] = t;
        t.x = pack2(vA[2], vB[2]); t.y = pack2(vA[3], vB[3]); sV23[tid] = t;
    }

    // ---- this thread's 2 queries (qa = qi, qb = qi+128), {q,q}-packed ----
    const int qi = blockIdx.x * QB + tid;
    ull qa[4], qb[4];
    {
        int ta = b*NS + qi, tb = ta + 128;
        float4 a0 = x4[ta*2], a1 = x4[ta*2+1];
        float4 b0 = x4[tb*2], b1 = x4[tb*2+1];
        float xra[8] = {a0.x,a0.y,a0.z,a0.w,a1.x,a1.y,a1.z,a1.w};
        float xrb[8] = {b0.x,b0.y,b0.z,b0.w,b1.x,b1.y,b1.z,b1.w};
#pragma unroll
        for (int d = 0; d < 4; d++) {
            float sa = 0.f, sb = 0.f;
#pragma unroll
            for (int e = 0; e < 8; e++) {
                float w = sWq[d*8 + e];
                sa += xra[e] * w;
                sb += xrb[e] * w;
            }
            qa[d] = pack2(sa * QSCALE, sa * QSCALE);
            qb[d] = pack2(sb * QSCALE, sb * QSCALE);
        }
    }
    __syncthreads();

    const ull ONE2 = pack2(1.f, 1.f);
    ull na0 = 0, na1 = 0, na2 = 0, na3 = 0;
    ull nb0 = 0, nb1 = 0, nb2 = 0, nb3 = 0;
    ull dap = 0, dbp = 0;

#pragma unroll 8
    for (int j = 0; j < NPAIR; j++) {
        ulonglong2 kA = sK01[j];     // {k0 pair | k1 pair}
        ulonglong2 kB = sK23[j];     // {k2 pair | k3 pair}
        ull sa = mul2p(qa[0], kA.x);
        ull sb = mul2p(qb[0], kA.x);
        sa = fma2p(qa[1], kA.y, sa);
        sb = fma2p(qb[1], kA.y, sb);
        sa = fma2p(qa[2], kB.x, sa);
        sb = fma2p(qb[2], kB.x, sb);
        sa = fma2p(qa[3], kB.y, sa);
        sb = fma2p(qb[3], kB.y, sb);
        float s0, s1, s2, s3;
        unpack2(sa, s0, s1);
        unpack2(sb, s2, s3);
        ull wa = pack2(ex2f(s0), ex2f(s1));
        ull wb = pack2(ex2f(s2), ex2f(s3));
        ulonglong2 vA = sV01[j];
        ulonglong2 vB = sV23[j];
        na0 = fma2p(wa, vA.x, na0);
        na1 = fma2p(wa, vA.y, na1);
        na2 = fma2p(wa, vB.x, na2);
        na3 = fma2p(wa, vB.y, na3);
        nb0 = fma2p(wb, vA.x, nb0);
        nb1 = fma2p(wb, vA.y, nb1);
        nb2 = fma2p(wb, vB.x, nb2);
        nb3 = fma2p(wb, vB.y, nb3);
        dap = fma2p(wa, ONE2, dap);
        dbp = fma2p(wb, ONE2, dbp);
    }

    // ---- reduce key-pair lanes, atomically accumulate ----
    {
        float lo, hi, s0, s1, s2, s3, dd;
        int a0 = (b*NS + qi)*2 + h;
        unpack2(na0, lo, hi); s0 = lo + hi;
        unpack2(na1, lo, hi); s1 = lo + hi;
        unpack2(na2, lo, hi); s2 = lo + hi;
        unpack2(na3, lo, hi); s3 = lo + hi;
        unpack2(dap, lo, hi); dd = lo + hi;
        float* pN = (float*)&g_accN[a0];
        atomicAdd(pN + 0, s0);
        atomicAdd(pN + 1, s1);
        atomicAdd(pN + 2, s2);
        atomicAdd(pN + 3, s3);
        atomicAdd(&g_accD[a0], dd);

        int a1 = a0 + 256;   // (qi+128)*2 + h
        unpack2(nb0, lo, hi); s0 = lo + hi;
        unpack2(nb1, lo, hi); s1 = lo + hi;
        unpack2(nb2, lo, hi); s2 = lo + hi;
        unpack2(nb3, lo, hi); s3 = lo + hi;
        unpack2(dbp, lo, hi); dd = lo + hi;
        pN = (float*)&g_accN[a1];
        atomicAdd(pN + 0, s0);
        atomicAdd(pN + 1, s1);
        atomicAdd(pN + 2, s2);
        atomicAdd(pN + 3, s3);
        atomicAdd(&g_accD[a1], dd);
    }

    // ---- cheap semaphore: release = syncthreads + tid0 fence+atom ----
    __syncthreads();                       // all CTA atomics issued
    const int cidx = b*NQBLK + blockIdx.x;
    if (tid == 0) {
        fence_gpu();                       // release (cumulative over barrier)
        s_old = atomicAdd(&g_cnt[cidx], 1u);
    }
    __syncthreads();
    if (s_old != NCONTRIB - 1) return;

    // acquire: tid0 fence, then CTA-wide visibility via barrier
    if (tid == 0) fence_gpu();
    __syncthreads();

    // ============ finalize 256 tokens (2 per thread) ============
#pragma unroll
    for (int half = 0; half < 2; half++) {
        int t = b*NS + blockIdx.x*QB + half*128 + tid;
        int a = t*2;
        float4 nA = __ldcg(&g_accN[a]);
        float4 nB = __ldcg(&g_accN[a+1]);
        float  dA = __ldcg(&g_accD[a]);
        float  dB = __ldcg(&g_accD[a+1]);
        float rA = rcpf(dA), rB = rcpf(dB);
        float o0 = nA.x*rA, o1 = nA.y*rA, o2 = nA.z*rA, o3 = nA.w*rA;
        float o4 = nB.x*rB, o5 = nB.y*rB, o6 = nB.z*rB, o7 = nB.w*rB;

        // c_u = cos(o_u + o_{u&3})
        float gc[8];
        gc[0] = __cosf(o0 + o0);
        gc[1] = __cosf(o1 + o1);
        gc[2] = __cosf(o2 + o2);
        gc[3] = __cosf(o3 + o3);
        gc[4] = __cosf(o4 + o0);
        gc[5] = __cosf(o5 + o1);
        gc[6] = __cosf(o6 + o2);
        gc[7] = __cosf(o7 + o3);

        // z_w = prod_{u<=w} gc_u (w>=1); z_0 = prod_{u=1..7}
        float z[8];
        float tp = gc[1];
        z[1] = gc[0] * tp;
#pragma unroll
        for (int w = 2; w < 8; w++) { tp *= gc[w]; z[w] = gc[0] * tp; }
        z[0] = tp;

        // out[t] = z @ Wo^T
        float rr[8];
#pragma unroll
        for (int f = 0; f < 8; f++) {
            float sacc = 0.f;
#pragma unroll
            for (int qq = 0; qq < 8; qq++) sacc += z[qq] * sWo[f*8 + qq];
            rr[f] = sacc;
        }
        float4* o4p = (float4*)out;
        o4p[t*2]   = make_float4(rr[0], rr[1], rr[2], rr[3]);
        o4p[t*2+1] = make_float4(rr[4], rr[5], rr[6], rr[7]);

        // restore zero-state for the next graph replay
        g_accN[a]   = make_float4(0.f, 0.f, 0.f, 0.f);
        g_accN[a+1] = make_float4(0.f, 0.f, 0.f, 0.f);
        g_accD[a]   = 0.f;
        g_accD[a+1] = 0.f;
    }
    if (tid == 0) g_cnt[cidx] = 0u;
}

// ============================================================
extern "C" void kernel_launch(void* const* d_in, const int* in_sizes, int n_in,
                              void* d_out, int out_size) {
    const float* x  = (const float*)d_in[0];
    const float* Wq = (const float*)d_in[1];
    const float* Wk = (const float*)d_in[2];
    const float* Wv = (const float*)d_in[3];
    const float* Wo = (const float*)d_in[4];
    float* out = (float*)d_out;

    fused_kernel<<<dim3(NQBLK, SPLITS, NBH), 128>>>(x, Wq, Wk, Wv, Wo, out);
}

// round 13
// speedup vs baseline: 1.1032x; 1.1032x over previous
#include <cuda_runtime.h>

#define NB 8
#define NS 2048
#define NE 8
#define NH 2
#define ND 4
#define NT (NB*NS)        // 16384 tokens
#define NBH (NB*NH)       // 16 (batch, head) pairs
#define SPLITS 8
#define KPS (NS/SPLITS)   // 256 keys per split
#define NPAIR (KPS/2)     // 128 key pairs
#define QB 256            // queries per CTA (2 per thread)

// log2(e) / sqrt(D) folded into q so scores feed ex2 directly
#define QSCALE 0.72134752044448169f

// Accumulators (zero at module load; quantum kernel re-zeroes after reading)
__device__ float4 g_accN[NT*NH];   // numerators, index = token*2 + head
__device__ float  g_accD[NT*NH];   // denominators

typedef unsigned long long ull;

// ---- packed f32x2 helpers ----
static __device__ __forceinline__ ull pack2(float a, float b) {
    ull r; asm("mov.b64 %0, {%1,%2};" : "=l"(r) : "f"(a), "f"(b)); return r;
}
static __device__ __forceinline__ void unpack2(ull v, float& a, float& b) {
    asm("mov.b64 {%0,%1}, %2;" : "=f"(a), "=f"(b) : "l"(v));
}
static __device__ __forceinline__ ull fma2p(ull a, ull b, ull c) {
    ull d; asm("fma.rn.f32x2 %0, %1, %2, %3;" : "=l"(d) : "l"(a), "l"(b), "l"(c)); return d;
}
static __device__ __forceinline__ ull mul2p(ull a, ull b) {
    ull d; asm("mul.rn.f32x2 %0, %1, %2;" : "=l"(d) : "l"(a), "l"(b)); return d;
}
static __device__ __forceinline__ float ex2f(float x) {
    float r; asm("ex2.approx.f32 %0, %1;" : "=f"(r) : "f"(x)); return r;
}
static __device__ __forceinline__ float rcpf(float x) {
    float r; asm("rcp.approx.f32 %0, %1;" : "=f"(r) : "f"(x)); return r;
}

// ============================================================
// Fused QKV + split-K softmax attention (R11-proven, unchanged).
// grid = (NS/QB, SPLITS, NBH), 128 threads, bounds(128,7).
// K/V staged key-pair-packed (SoA, conflict-free LDS.128).
// Atomic (REDG) output into global accumulators.
// ============================================================
__global__ void __launch_bounds__(128, 7) attn_kernel(const float* __restrict__ x,
                                                      const float* __restrict__ Wq,
                                                      const float* __restrict__ Wk,
                                                      const float* __restrict__ Wv) {
    __shared__ float sWq[32], sWk[32], sWv[32];   // this head's 4 rows (4x8)
    __shared__ ulonglong2 sK01[NPAIR];
    __shared__ ulonglong2 sK23[NPAIR];
    __shared__ ulonglong2 sV01[NPAIR];
    __shared__ ulonglong2 sV23[NPAIR];

    const int bh    = blockIdx.z;
    const int split = blockIdx.y;
    const int tid   = threadIdx.x;
    const int b     = bh >> 1;
    const int h     = bh & 1;

    if (tid < 32) {
        sWq[tid] = Wq[h*32 + tid];
        sWk[tid] = Wk[h*32 + tid];
        sWv[tid] = Wv[h*32 + tid];
    }
    __syncthreads();

    const float4* x4 = (const float4*)x;

    // ---- stage one key pair per thread (keys 2*tid, 2*tid+1) ----
    {
        int tokA = b*NS + split*KPS + 2*tid;
        float4 a0 = x4[tokA*2], a1 = x4[tokA*2+1];
        float4 b0 = x4[tokA*2+2], b1 = x4[tokA*2+3];
        float xra[8] = {a0.x,a0.y,a0.z,a0.w,a1.x,a1.y,a1.z,a1.w};
        float xrb[8] = {b0.x,b0.y,b0.z,b0.w,b1.x,b1.y,b1.z,b1.w};
        float kA[4], vA[4], kB[4], vB[4];
#pragma unroll
        for (int d = 0; d < 4; d++) {
            float ka = 0.f, va = 0.f, kb = 0.f, vb = 0.f;
#pragma unroll
            for (int e = 0; e < 8; e++) {
                float wk = sWk[d*8 + e], wv = sWv[d*8 + e];
                ka += xra[e] * wk;  va += xra[e] * wv;
                kb += xrb[e] * wk;  vb += xrb[e] * wv;
            }
            kA[d] = ka; vA[d] = va; kB[d] = kb; vB[d] = vb;
        }
        ulonglong2 t;
        t.x = pack2(kA[0], kB[0]); t.y = pack2(kA[1], kB[1]); sK01[tid] = t;
        t.x = pack2(kA[2], kB[2]); t.y = pack2(kA[3], kB[3]); sK23[tid] = t;
        t.x = pack2(vA[0], vB[0]); t.y = pack2(vA[1], vB[1]); sV01[tid] = t;
        t.x = pack2(vA[2], vB[2]); t.y = pack2(vA[3], vB[3]); sV23[tid] = t;
    }

    // ---- this thread's 2 queries (qa = qi, qb = qi+128), {q,q}-packed ----
    const int qi = blockIdx.x * QB + tid;
    ull qa[4], qb[4];
    {
        int ta = b*NS + qi, tb = ta + 128;
        float4 a0 = x4[ta*2], a1 = x4[ta*2+1];
        float4 b0 = x4[tb*2], b1 = x4[tb*2+1];
        float xra[8] = {a0.x,a0.y,a0.z,a0.w,a1.x,a1.y,a1.z,a1.w};
        float xrb[8] = {b0.x,b0.y,b0.z,b0.w,b1.x,b1.y,b1.z,b1.w};
#pragma unroll
        for (int d = 0; d < 4; d++) {
            float sa = 0.f, sb = 0.f;
#pragma unroll
            for (int e = 0; e < 8; e++) {
                float w = sWq[d*8 + e];
                sa += xra[e] * w;
                sb += xrb[e] * w;
            }
            qa[d] = pack2(sa * QSCALE, sa * QSCALE);
            qb[d] = pack2(sb * QSCALE, sb * QSCALE);
        }
    }
    __syncthreads();

    const ull ONE2 = pack2(1.f, 1.f);
    ull na0 = 0, na1 = 0, na2 = 0, na3 = 0;
    ull nb0 = 0, nb1 = 0, nb2 = 0, nb3 = 0;
    ull dap = 0, dbp = 0;

#pragma unroll 8
    for (int j = 0; j < NPAIR; j++) {
        ulonglong2 kA = sK01[j];     // {k0 pair | k1 pair}
        ulonglong2 kB = sK23[j];     // {k2 pair | k3 pair}
        ull sa = mul2p(qa[0], kA.x);
        ull sb = mul2p(qb[0], kA.x);
        sa = fma2p(qa[1], kA.y, sa);
        sb = fma2p(qb[1], kA.y, sb);
        sa = fma2p(qa[2], kB.x, sa);
        sb = fma2p(qb[2], kB.x, sb);
        sa = fma2p(qa[3], kB.y, sa);
        sb = fma2p(qb[3], kB.y, sb);
        float s0, s1, s2, s3;
        unpack2(sa, s0, s1);
        unpack2(sb, s2, s3);
        ull wa = pack2(ex2f(s0), ex2f(s1));
        ull wb = pack2(ex2f(s2), ex2f(s3));
        ulonglong2 vA = sV01[j];
        ulonglong2 vB = sV23[j];
        na0 = fma2p(wa, vA.x, na0);
        na1 = fma2p(wa, vA.y, na1);
        na2 = fma2p(wa, vB.x, na2);
        na3 = fma2p(wa, vB.y, na3);
        nb0 = fma2p(wb, vA.x, nb0);
        nb1 = fma2p(wb, vA.y, nb1);
        nb2 = fma2p(wb, vB.x, nb2);
        nb3 = fma2p(wb, vB.y, nb3);
        dap = fma2p(wa, ONE2, dap);
        dbp = fma2p(wb, ONE2, dbp);
    }

    // ---- reduce key-pair lanes, atomically accumulate ----
    {
        float lo, hi, s0, s1, s2, s3, dd;
        int a0 = (b*NS + qi)*2 + h;
        unpack2(na0, lo, hi); s0 = lo + hi;
        unpack2(na1, lo, hi); s1 = lo + hi;
        unpack2(na2, lo, hi); s2 = lo + hi;
        unpack2(na3, lo, hi); s3 = lo + hi;
        unpack2(dap, lo, hi); dd = lo + hi;
        float* pN = (float*)&g_accN[a0];
        atomicAdd(pN + 0, s0);
        atomicAdd(pN + 1, s1);
        atomicAdd(pN + 2, s2);
        atomicAdd(pN + 3, s3);
        atomicAdd(&g_accD[a0], dd);

        int a1 = a0 + 256;   // (qi+128)*2 + h
        unpack2(nb0, lo, hi); s0 = lo + hi;
        unpack2(nb1, lo, hi); s1 = lo + hi;
        unpack2(nb2, lo, hi); s2 = lo + hi;
        unpack2(nb3, lo, hi); s3 = lo + hi;
        unpack2(dbp, lo, hi); dd = lo + hi;
        pN = (float*)&g_accN[a1];
        atomicAdd(pN + 0, s0);
        atomicAdd(pN + 1, s1);
        atomicAdd(pN + 2, s2);
        atomicAdd(pN + 3, s3);
        atomicAdd(&g_accD[a1], dd);
    }
}

// ============================================================
// Finalize, shuffle-free: one thread per (token, head); each
// thread loads BOTH heads' accumulators (loads fired first,
// overlapped with sWo staging), computes all 8 cosines itself,
// writes its head's 4 features, re-zeroes its own slots.
// z_w = prod_{u<=w} cos(o_u + o_{u&3}) (w>=1); z_0 = prod_{u=1..7}.
// ============================================================
__global__ void __launch_bounds__(128) quantum_kernel(const float* __restrict__ Wo,
                                                      float* __restrict__ out) {
    __shared__ float sWo[64];
    int tid = threadIdx.x;
    int gid = blockIdx.x * 128 + tid;   // = token*2 + head
    int t = gid >> 1;
    int h = gid & 1;

    // fire long-latency loads immediately: both heads of this token
    float4 n0 = g_accN[t*2];       // head 0 numerators
    float4 n1 = g_accN[t*2 + 1];   // head 1 numerators
    float  d0 = g_accD[t*2];
    float  d1 = g_accD[t*2 + 1];

    if (tid < 64) sWo[tid] = Wo[tid];
    __syncthreads();

    float r0 = rcpf(d0), r1 = rcpf(d1);
    float o0 = n0.x*r0, o1 = n0.y*r0, o2 = n0.z*r0, o3 = n0.w*r0;
    float o4 = n1.x*r1, o5 = n1.y*r1, o6 = n1.z*r1, o7 = n1.w*r1;

    // c_u = cos(o_u + o_{u&3})
    float gc[8];
    gc[0] = __cosf(o0 + o0);
    gc[1] = __cosf(o1 + o1);
    gc[2] = __cosf(o2 + o2);
    gc[3] = __cosf(o3 + o3);
    gc[4] = __cosf(o4 + o0);
    gc[5] = __cosf(o5 + o1);
    gc[6] = __cosf(o6 + o2);
    gc[7] = __cosf(o7 + o3);

    // z products
    float z[8];
    float tp = gc[1];
    z[1] = gc[0] * tp;
#pragma unroll
    for (int w = 2; w < 8; w++) { tp *= gc[w]; z[w] = gc[0] * tp; }
    z[0] = tp;

    // this thread's 4 output features f = h*4+i
    float rr[4];
#pragma unroll
    for (int i = 0; i < 4; i++) {
        float sacc = 0.f;
#pragma unroll
        for (int qq = 0; qq < 8; qq++) sacc += z[qq] * sWo[(h*4 + i)*8 + qq];
        rr[i] = sacc;
    }
    ((float4*)out)[gid] = make_float4(rr[0], rr[1], rr[2], rr[3]);

    // restore zero-state for the next replay (each thread its own slot)
    g_accN[gid] = make_float4(0.f, 0.f, 0.f, 0.f);
    g_accD[gid] = 0.f;
}

// ============================================================
extern "C" void kernel_launch(void* const* d_in, const int* in_sizes, int n_in,
                              void* d_out, int out_size) {
    const float* x  = (const float*)d_in[0];
    const float* Wq = (const float*)d_in[1];
    const float* Wk = (const float*)d_in[2];
    const float* Wv = (const float*)d_in[3];
    const float* Wo = (const float*)d_in[4];
    float* out = (float*)d_out;

    attn_kernel<<<dim3(NS/QB, SPLITS, NBH), 128>>>(x, Wq, Wk, Wv);
    quantum_kernel<<<NT*NH/128, 128>>>(Wo, out);
}